// round 1
// baseline (speedup 1.0000x reference)
#include <cuda_runtime.h>

#define EPS_ 1e-4f

#define B_     2048
#define N_     64
#define E_     512
#define C_     6
#define CN_    7
#define K_     20
#define DSELF_ 120
#define DNEI_  48
#define ROWS_  (B_ * N_)        /* 131072 */
#define XSIZE_ (B_ * K_ * E_)   /* 20971520 */

// ---------------- device scratch (no allocations allowed) ----------------
__device__ float g_anchor[C_ * K_ * E_];   // [c,k,e] anchor partial + bias
__device__ int   g_cnt[CN_];               // per-class row counts
__device__ int   g_idx[CN_ * ROWS_];       // per-class row index lists

// ---------------- f32x2 helpers ----------------
typedef unsigned long long u64;

__device__ __forceinline__ u64 dup2(float x) {
    u64 r; asm("mov.b64 %0, {%1, %1};" : "=l"(r) : "f"(x)); return r;
}
__device__ __forceinline__ void fma2(u64 &d, u64 a, u64 b) {
    asm("fma.rn.f32x2 %0, %1, %2, %0;" : "+l"(d) : "l"(a), "l"(b));
}
__device__ __forceinline__ void unpack2(u64 v, float &lo, float &hi) {
    asm("mov.b64 {%0, %1}, %2;" : "=f"(lo), "=f"(hi) : "l"(v));
}

union F4U2 { float4 f4; u64 u[2]; };

__device__ __forceinline__ float srecip(float x) {
    float d = x + (x >= 0.0f ? EPS_ : -EPS_);
    return __fdividef(1.0f, d);
}

// ---------------- kernel 0: zero counters ----------------
__global__ void k_zero() {
    if (threadIdx.x < CN_) g_cnt[threadIdx.x] = 0;
}

// ---------------- kernel 1: anchor[c,k,e] = it[c,k]·W_self[c,48:120] + b_self[c] ----------------
__global__ void k_anchor(const float* __restrict__ it,
                         const float* __restrict__ Ws,
                         const float* __restrict__ bs) {
    __shared__ float its[72];
    int ck = blockIdx.x;          // 0..119
    int c  = ck / K_;
    int t  = threadIdx.x;         // e
    if (t < 18) ((float4*)its)[t] = ((const float4*)(it + ck * 72))[t];
    __syncthreads();
    const float* W = Ws + c * DSELF_ * E_ + 48 * E_ + t;
    float a0 = 0.f, a1 = 0.f, a2 = 0.f, a3 = 0.f;
#pragma unroll
    for (int j = 0; j < 72; j += 4) {
        a0 += its[j + 0] * W[(j + 0) * E_];
        a1 += its[j + 1] * W[(j + 1) * E_];
        a2 += its[j + 2] * W[(j + 2) * E_];
        a3 += its[j + 3] * W[(j + 3) * E_];
    }
    g_anchor[ck * E_ + t] = (a0 + a1) + (a2 + a3) + bs[c * E_ + t];
}

// ---------------- kernel 2: bucket rows by neighbor label ----------------
__global__ void k_bucket(const int* __restrict__ lab) {
    __shared__ int scnt[CN_], sbase[CN_];
    int t = threadIdx.x;
    if (t < CN_) scnt[t] = 0;
    __syncthreads();
    int r = blockIdx.x * 256 + t;
    int c = lab[r];
    int local = atomicAdd(&scnt[c], 1);
    __syncthreads();
    if (t < CN_) sbase[t] = atomicAdd(&g_cnt[t], scnt[t]);
    __syncthreads();
    g_idx[c * ROWS_ + sbase[c] + local] = r;
}

// ---------------- kernel 3: x[b,k,e] = obs[b]·W_self[lab,0:48,e] + anchor[lab,k,e] ----------------
__global__ void k_self(const float* __restrict__ obs,
                       const float* __restrict__ Ws,
                       const int*   __restrict__ lab,
                       float*       __restrict__ outx) {
    __shared__ float os[48];
    int b = blockIdx.x;
    int t = threadIdx.x;          // e
    if (t < 12) ((float4*)os)[t] = ((const float4*)(obs + b * 48))[t];
    int c = lab[b];
    __syncthreads();
    const float* W = Ws + c * DSELF_ * E_ + t;
    float a0 = 0.f, a1 = 0.f, a2 = 0.f, a3 = 0.f;
#pragma unroll
    for (int j = 0; j < 48; j += 4) {
        a0 += os[j + 0] * W[(j + 0) * E_];
        a1 += os[j + 1] * W[(j + 1) * E_];
        a2 += os[j + 2] * W[(j + 2) * E_];
        a3 += os[j + 3] * W[(j + 3) * E_];
    }
    float s = (a0 + a1) + (a2 + a3);
    const float* ap = g_anchor + c * K_ * E_ + t;
    float* o = outx + b * K_ * E_ + t;
#pragma unroll
    for (int k = 0; k < K_; k++) o[k * E_] = s + ap[k * E_];
}

// ---------------- kernel 4: class-sorted neighbor GEMM ----------------
// Block: 256 threads = 16(tx: e) x 16(ty: rows). Tile: 128 rows x 128 e, K=48 full.
// Thread tile: 8 rows x 8 e (4 f32x2 pairs), accumulate with fma.rn.f32x2.
__global__ void __launch_bounds__(256, 2)
k_nei(const float* __restrict__ neis,
      const float* __restrict__ Wn,
      const float* __restrict__ bn,
      float*       __restrict__ outn) {
    __shared__ float w_s[48 * 128];   // [j][e]      24 KB
    __shared__ float a_s[48 * 128];   // [j][row]    24 KB (transposed acts)

    int c    = blockIdx.z;
    int cnt  = g_cnt[c];
    int base = blockIdx.y * 128;
    if (base >= cnt) return;
    int e0  = blockIdx.x * 128;
    int tid = threadIdx.x;
    int tx  = tid & 15;
    int ty  = tid >> 4;

    // --- load W tile: 48 x 128 floats = 1536 float4, 6 per thread ---
    const float* Wc = Wn + c * DNEI_ * E_;
#pragma unroll
    for (int t = 0; t < 6; t++) {
        int lin = t * 256 + tid;          // 0..1535
        int j   = lin >> 5;
        int e4  = lin & 31;
        float4 v = *(const float4*)(Wc + j * E_ + e0 + e4 * 4);
        *(float4*)&w_s[j * 128 + e4 * 4] = v;
    }

    // --- load activation tile (gathered rows, fused signed-reciprocal), transpose into a_s ---
    {
        int i  = tid >> 1;                // row within tile 0..127
        int h  = tid & 1;                 // half of the 48 features
        int gi = base + i;
        int rr = (gi < cnt) ? g_idx[c * ROWS_ + gi] : -1;
        const float* src = neis + (long long)rr * 48 + h * 24;
#pragma unroll
        for (int t = 0; t < 6; t++) {
            float v0 = 0.f, v1 = 0.f, v2 = 0.f, v3 = 0.f;
            if (rr >= 0) {
                float4 v = *(const float4*)(src + t * 4);
                v0 = srecip(v.x); v1 = srecip(v.y);
                v2 = srecip(v.z); v3 = srecip(v.w);
            }
            int j0 = h * 24 + t * 4;
            a_s[(j0 + 0) * 128 + i] = v0;
            a_s[(j0 + 1) * 128 + i] = v1;
            a_s[(j0 + 2) * 128 + i] = v2;
            a_s[(j0 + 3) * 128 + i] = v3;
        }
    }
    __syncthreads();

    // --- init accumulators with bias ---
    F4U2 b0, b1;
    b0.f4 = *(const float4*)(bn + c * E_ + e0 + tx * 4);
    b1.f4 = *(const float4*)(bn + c * E_ + e0 + 64 + tx * 4);
    u64 acc[8][4];
#pragma unroll
    for (int r = 0; r < 8; r++) {
        acc[r][0] = b0.u[0]; acc[r][1] = b0.u[1];
        acc[r][2] = b1.u[0]; acc[r][3] = b1.u[1];
    }

    // --- main loop over K=48 ---
#pragma unroll 8
    for (int j = 0; j < 48; j++) {
        F4U2 w0, w1;
        w0.f4 = *(const float4*)&w_s[j * 128 + tx * 4];
        w1.f4 = *(const float4*)&w_s[j * 128 + 64 + tx * 4];
        float4 a0 = *(const float4*)&a_s[j * 128 + ty * 8];
        float4 a1 = *(const float4*)&a_s[j * 128 + ty * 8 + 4];
        u64 ad[8];
        ad[0] = dup2(a0.x); ad[1] = dup2(a0.y); ad[2] = dup2(a0.z); ad[3] = dup2(a0.w);
        ad[4] = dup2(a1.x); ad[5] = dup2(a1.y); ad[6] = dup2(a1.z); ad[7] = dup2(a1.w);
#pragma unroll
        for (int r = 0; r < 8; r++) {
            fma2(acc[r][0], ad[r], w0.u[0]);
            fma2(acc[r][1], ad[r], w0.u[1]);
            fma2(acc[r][2], ad[r], w1.u[0]);
            fma2(acc[r][3], ad[r], w1.u[1]);
        }
    }

    // --- epilogue: scatter-store rows ---
#pragma unroll
    for (int r = 0; r < 8; r++) {
        int ii = base + ty * 8 + r;
        if (ii < cnt) {
            int rg = g_idx[c * ROWS_ + ii];
            float* o = outn + (long long)rg * E_ + e0;
            float4 o0, o1;
            unpack2(acc[r][0], o0.x, o0.y);
            unpack2(acc[r][1], o0.z, o0.w);
            unpack2(acc[r][2], o1.x, o1.y);
            unpack2(acc[r][3], o1.z, o1.w);
            *(float4*)(o + tx * 4)      = o0;
            *(float4*)(o + 64 + tx * 4) = o1;
        }
    }
}

// ---------------- launch ----------------
extern "C" void kernel_launch(void* const* d_in, const int* in_sizes, int n_in,
                              void* d_out, int out_size) {
    const float* obs  = (const float*)d_in[0];
    const float* neis = (const float*)d_in[1];
    const float* it   = (const float*)d_in[2];
    const float* Ws   = (const float*)d_in[3];
    const float* bs   = (const float*)d_in[4];
    const float* Wn   = (const float*)d_in[5];
    const float* bn   = (const float*)d_in[6];
    const int*   slab = (const int*)d_in[7];
    const int*   nlab = (const int*)d_in[8];

    float* outx = (float*)d_out;            // [B, K, E]
    float* outn = outx + XSIZE_;            // [B, N, E]

    k_zero<<<1, 32>>>();
    k_anchor<<<C_ * K_, 512>>>(it, Ws, bs);
    k_bucket<<<ROWS_ / 256, 256>>>(nlab);
    k_self<<<B_, 512>>>(obs, Ws, slab, outx);
    dim3 g(4, ROWS_ / 128, CN_);
    k_nei<<<g, 256>>>(neis, Wn, bn, outn);
}